// round 17
// baseline (speedup 1.0000x reference)
#include <cuda_runtime.h>

#define DD     10000   // hypervector dimensions
#define TT     128     // time steps
#define CC     32      // channels
#define BB     4       // batch
#define NCLS   10
#define NWIN   125     // T - NGRAM + 1
#define TD     136     // d-tile per block (74 * 136 = 10064 covers 10000)
#define NTILES 74
#define NBLK   (NTILES * BB)   // 296 = 2 * 148 -> exactly 2 blocks per SM
#define NCOLS  160     // 5 col-warps (TD + 3 halo = 139 used)
#define CSTR   33      // words per column (32 data + 1 pad; 33 % 32 == 1 -> conflict-free)

// Scratch (device globals — no allocation allowed; zero-initialized at load)
__device__ float    g_partial[BB * NTILES * NCLS];
__device__ unsigned g_ticket;

// PTX prmt with sign-replicate mode (selector nibble bit3). The __byte_perm
// intrinsic masks bit3 (proven by R15's corruption); inline asm does not.
// Pool bytes: 0-3 = a, 4-7 = b. Selector n*0x1111+0x8880 -> byte0 = pool byte
// n, bytes1-3 = sign of pool byte n  ==> sign-extended int8 in ONE instruction.
__device__ __forceinline__ int prmt_sx(unsigned a, unsigned b, unsigned sel) {
    unsigned r;
    asm("prmt.b32 %0, %1, %2, %3;" : "=r"(r) : "r"(a), "r"(b), "r"(sel));
    return (int)r;
}

// ---------------------------------------------------------------------------
// Fused kernel, 640 threads = 20 warps = 4 t-quarters (q) x 5 col-warps (cw).
// col = cw*32+lane in [0,160); d-column dp = (d0-3+col) mod DD. Tile covers
// outputs d0..d0+135 (last tile partial; guarded). Samples tile column-major
// word-packed (stride 33 words -> conflict-free 32-bit LDS/STS).
// R17 delta vs R16: phase-B operand extraction via pool-indexed prmt.b32
// (sign-replicate mode, inline asm): window j, neighbor k needs sample
// t=4g+j+k == pool byte j+k of {c_k (word g), m_k (word g+1)} -> 1 PRMT,
// replacing funnelshift alignment + shl/asr extracts (~150 fewer instr/thr).
// ---------------------------------------------------------------------------
__global__ __launch_bounds__(640, 2) void k_fused(
    const float* __restrict__ x,
    const float* __restrict__ signals_w,
    const float* __restrict__ timestamps_w,
    const float* __restrict__ classify_w,
    float* __restrict__ out)
{
    __shared__ __align__(16) unsigned cnt_s[TT * 8];   // 4 KB packed histograms
    __shared__ int sw_s[6][NCOLS];                     // packed signal signs
    __shared__ unsigned ssw[NCOLS * CSTR];             // 21.1 KB word-packed samples
    __shared__ int   acc_s[4][NCOLS];                  // window-quarter partials
    __shared__ float wsum2[NCLS][5];                   // per-(class, col-warp)
    __shared__ int   last_flag;

    const int tid  = threadIdx.x;
    const int w    = tid >> 5;          // warp 0..19
    const int lane = tid & 31;
    const int cw   = w % 5;             // col-warp 0..4
    const int q    = w / 5;             // t-quarter 0..3 -> t in [32q, 32q+32)
    const int col  = cw * 32 + lane;    // 0..159
    const int tile = blockIdx.x;
    const int b    = blockIdx.y;
    const int d0   = tile * TD;
    const int t0   = q * 32;

    int dp = d0 - 3 + col;              // roll column (mod DD)
    if (dp < 0)   dp += DD;
    if (dp >= DD) dp -= DD;

    // --- Pre: 32 timestamp sign bits -> one word (all LDG latency here) ---
    unsigned tsbits = 0;
#pragma unroll
    for (int tt = 0; tt < 32; tt++)
        tsbits |= (__float_as_uint(timestamps_w[(t0 + tt) * DD + dp]) >> 31) << tt;

    if (q == 0) {
        if (col < TT) {
            // --- Histogram for t = col (packed: 21 levels, <=32 per byte) ---
            uint4 z = make_uint4(0u, 0u, 0u, 0u);
            *(uint4*)&cnt_s[col * 8]     = z;
            *(uint4*)&cnt_s[col * 8 + 4] = z;
            const float4* xp = (const float4*)(x + (b * TT + col) * CC);
#pragma unroll
            for (int c4 = 0; c4 < CC / 4; c4++) {
                float4 v4 = xp[c4];
                float vv[4] = {v4.x, v4.y, v4.z, v4.w};
#pragma unroll
                for (int j = 0; j < 4; j++) {
                    float v = (vv[j] / 20.0f) * 20.0f;   // mirrors reference fp
                    int iv = __float2int_rn(v);          // round half-to-even
                    iv = iv < 0 ? 0 : (iv > 20 ? 20 : iv);
                    cnt_s[col * 8 + (iv >> 2)] += 1u << ((iv & 3) * 8);
                }
            }
        }
    } else if (q == 1) {
        // --- Pack column col's 21 signal signs as int8 bytes (+1 / -1) ---
        unsigned sw[6] = {0u, 0u, 0u, 0u, 0u, 0u};
#pragma unroll
        for (int l = 0; l < 21; l++) {
            unsigned neg  = __float_as_uint(signals_w[l * DD + dp]) >> 31;
            unsigned byte = neg ? 0xFFu : 0x01u;
            sw[l >> 2] |= byte << ((l & 3) * 8);
        }
#pragma unroll
        for (int l = 0; l < 6; l++) sw_s[l][col] = (int)sw[l];
    } else if (q == 2) {
        ssw[col * CSTR + 32] = 0u;      // zero pad word: windows >=125 vanish
    }
    __syncthreads();

    const int sp0 = sw_s[0][col], sp1 = sw_s[1][col], sp2 = sw_s[2][col];
    const int sp3 = sw_s[3][col], sp4 = sw_s[4][col], sp5 = sw_s[5][col];

    // --- Phase A: 32 t-rows via dp4a; PRMT byte pack; 8 conflict-free STS.32 ---
#pragma unroll
    for (int ww = 0; ww < 8; ww++) {
        unsigned pk = 0;
#pragma unroll
        for (int u = 0; u < 4; u++) {
            const int t = t0 + 4 * ww + u;
            uint4 ca = *(const uint4*)&cnt_s[t * 8];       // broadcast LDS
            uint2 cb = *(const uint2*)&cnt_s[t * 8 + 4];
            int a = 0;
            a = __dp4a((int)ca.x, sp0, a);
            a = __dp4a((int)ca.y, sp1, a);
            a = __dp4a((int)ca.z, sp2, a);
            a = __dp4a((int)ca.w, sp3, a);
            a = __dp4a((int)cb.x, sp4, a);
            a = __dp4a((int)cb.y, sp5, a);
            int m = (int)(tsbits << (31 - (4 * ww + u))) >> 31;  // 0 or -1
            int v = (a ^ m) - m;                                 // +-a, |v| <= 32
            const unsigned sel = (u == 0) ? 0x3214u : (u == 1) ? 0x3240u
                               : (u == 2) ? 0x3410u : 0x4210u;   // nibbles <= 7: OK
            pk = __byte_perm(pk, (unsigned)v, sel);     // insert byte u
        }
        ssw[col * CSTR + q * 8 + ww] = pk;              // conflict-free (stride 33)
    }
    __syncthreads();

    // --- Phase B: 8 window groups; pool-indexed PRMT sign-extended operands ---
    int acc0 = 0, acc1 = 0;
    if (col < TD) {                    // halo cols 136..159 skip
        const int g0 = 8 * q;          // groups [8q, 8q+8), windows [32q, 32q+32)
        unsigned c0 = ssw[(col + 0) * CSTR + g0];
        unsigned c1 = ssw[(col + 1) * CSTR + g0];
        unsigned c2 = ssw[(col + 2) * CSTR + g0];
        unsigned c3 = ssw[(col + 3) * CSTR + g0];
#pragma unroll
        for (int gg = 0; gg < 8; gg++) {
            const int g = g0 + gg;
            unsigned m0 = ssw[(col + 0) * CSTR + g + 1];   // word g+1 (<= 32)
            unsigned m1 = ssw[(col + 1) * CSTR + g + 1];
            unsigned m2 = ssw[(col + 2) * CSTR + g + 1];
            unsigned m3 = ssw[(col + 3) * CSTR + g + 1];
#pragma unroll
            for (int j = 0; j < 4; j++) {
                // window i=4g+j, neighbor k -> sample t=i+k = pool byte j+k
                int b0 = prmt_sx(c0, m0, (unsigned)(j + 0) * 0x1111u + 0x8880u);
                int b1 = prmt_sx(c1, m1, (unsigned)(j + 1) * 0x1111u + 0x8880u);
                int b2 = prmt_sx(c2, m2, (unsigned)(j + 2) * 0x1111u + 0x8880u);
                int b3 = prmt_sx(c3, m3, (unsigned)(j + 3) * 0x1111u + 0x8880u);
                int p = b0 * b1 * b2 * b3;              // exact; pad rows -> 0
                if (j & 1) acc1 += p; else acc0 += p;
            }
            c0 = m0; c1 = m1; c2 = m2; c3 = m3;
        }
    }
    acc_s[q][col] = acc0 + acc1;
    __syncthreads();

    // --- Phase C: all 20 warps; class split 3/3/3/1 over q; col over cw ---
    {
        const int n0 = 3 * q;
        const int at = acc_s[0][col] + acc_s[1][col] + acc_s[2][col] + acc_s[3][col];
        const bool owns = (col < TD) && (d0 + col < DD);   // last tile partial
        float val[3];
#pragma unroll
        for (int j = 0; j < 3; j++) {
            const int n = n0 + j;
            float wv = (n < NCLS && owns) ? classify_w[n * DD + d0 + col] : 0.f;
            val[j] = (at > 0) ? wv : -wv;   // non-owning lanes contribute 0
        }
#pragma unroll
        for (int j = 0; j < 3; j++) {
#pragma unroll
            for (int off = 16; off > 0; off >>= 1)
                val[j] += __shfl_down_sync(0xffffffffu, val[j], off);
        }
        if (lane == 0) {
#pragma unroll
            for (int j = 0; j < 3; j++) {
                const int n = n0 + j;
                if (n < NCLS) wsum2[n][cw] = val[j];
            }
        }
    }
    __syncthreads();
    if (tid < NCLS) {
        float s = wsum2[tid][0] + wsum2[tid][1] + wsum2[tid][2]
                + wsum2[tid][3] + wsum2[tid][4];
        g_partial[(b * NTILES + tile) * NCLS + tid] = s;
    }

    // --- Deterministic last-block final reduction (fixed tile order) ---
    __threadfence();
    __syncthreads();
    if (tid == 0) {
        unsigned tk = atomicAdd(&g_ticket, 1u);
        last_flag = (tk == NBLK - 1);
    }
    __syncthreads();
    if (last_flag) {
        if (tid == 0) g_ticket = 0;        // reset for next graph replay
        __threadfence();
        if (tid < BB * NCLS) {
            int bb = tid / NCLS, n = tid % NCLS;
            float s = 0.f;
#pragma unroll 8
            for (int t2 = 0; t2 < NTILES; t2++)
                s += g_partial[(bb * NTILES + t2) * NCLS + n];
            out[bb * NCLS + n] = s;
        }
    }
}

extern "C" void kernel_launch(void* const* d_in, const int* in_sizes, int n_in,
                              void* d_out, int out_size) {
    const float* x            = (const float*)d_in[0];  // [4,128,32]
    const float* signals_w    = (const float*)d_in[1];  // [21,10000]
    // d_in[2] = channels_w : dead bind in reference, intentionally unused
    const float* timestamps_w = (const float*)d_in[3];  // [128,10000]
    const float* classify_w   = (const float*)d_in[4];  // [10,10000]
    float* out = (float*)d_out;                         // [4,10] fp32

    k_fused<<<dim3(NTILES, BB), 640>>>(x, signals_w, timestamps_w, classify_w, out);
}